// round 10
// baseline (speedup 1.0000x reference)
#include <cuda_runtime.h>
#include <cuda_fp16.h>
#include <cstdint>

// ---------------------------------------------------------------------------
// Problem constants
// ---------------------------------------------------------------------------
constexpr int Bn   = 128;
constexpr int Tn   = 128;
constexpr int Cn   = 256;
constexpr int Hn   = 4;
constexpr int Ln   = 6;
constexpr int Vn   = 10000;
constexpr int HSn  = 64;
constexpr int DFFn = 1024;
constexpr int NTOK = Bn * Tn;
constexpr int QKVN = 3 * Cn;       // 768

// ---------------------------------------------------------------------------
// Scratch (device globals -- allocation-free per harness rules)
// ---------------------------------------------------------------------------
__device__ float  g_x   [NTOK * Cn];      // residual stream (fp32)
__device__ __half g_h   [NTOK * Cn];      // LN output (fp16, GEMM A)
__device__ float  g_qkv [NTOK * QKVN];    // QKV GEMM out (fp32, attn input)
__device__ __half g_att [NTOK * Cn];      // attn output (fp16, GEMM A)
__device__ __half g_ffn [NTOK * DFFn];    // relu output (fp16, GEMM A)
// fp16, TRANSPOSED ([N,K] K-major) weight copies for GEMM B operand
__device__ __half g_qkvw[Ln * Cn * QKVN];
__device__ __half g_projw[Ln * Cn * Cn];
__device__ __half g_w1  [Ln * Cn * DFFn];
__device__ __half g_w2  [Ln * DFFn * Cn];
__device__ __half g_lmw [Cn * Vn];

// ---------------------------------------------------------------------------
// Prepack: transpose + fp16 convert. src [Ksz,Nsz] -> dst [Nsz,Ksz], batched.
// ---------------------------------------------------------------------------
__global__ void trt_kernel(const float* __restrict__ src, __half* __restrict__ dst,
                           int Ksz, int Nsz, size_t sStride, size_t dStride) {
    __shared__ float tile[32][33];
    const float* s = src + blockIdx.z * sStride;
    __half*      d = dst + blockIdx.z * dStride;
    int k0 = blockIdx.y * 32, n0 = blockIdx.x * 32;
    int tx = threadIdx.x, ty = threadIdx.y;     // 32 x 8
    #pragma unroll
    for (int j = 0; j < 32; j += 8) {
        int k = k0 + ty + j, n = n0 + tx;
        if (k < Ksz && n < Nsz) tile[ty + j][tx] = s[(size_t)k * Nsz + n];
    }
    __syncthreads();
    #pragma unroll
    for (int j = 0; j < 32; j += 8) {
        int n = n0 + ty + j, k = k0 + tx;
        if (n < Nsz && k < Ksz)
            d[(size_t)n * Ksz + k] = __float2half_rn(tile[tx][ty + j]);
    }
}

// ---------------------------------------------------------------------------
// Embedding
// ---------------------------------------------------------------------------
__global__ void embed_kernel(const int* __restrict__ idx,
                             const float* __restrict__ tok,
                             const float* __restrict__ pos) {
    int token = blockIdx.x;
    int c     = threadIdx.x;
    int t     = token % Tn;
    int id    = idx[token];
    g_x[token * Cn + c] = tok[id * Cn + c] + pos[t * Cn + c];
}

// ---------------------------------------------------------------------------
// LayerNorm (shuffle reductions), fp16 output (feeds GEMM A operand)
// ---------------------------------------------------------------------------
__global__ void __launch_bounds__(Cn)
ln_kernel(const float* __restrict__ in, const float* __restrict__ gg,
          const float* __restrict__ bb, __half* __restrict__ out) {
    __shared__ float part[8];
    int token = blockIdx.x;
    int c     = threadIdx.x;
    int lane  = c & 31, w = c >> 5;
    float v = in[token * Cn + c];

    float s = v;
    #pragma unroll
    for (int o = 16; o; o >>= 1) s += __shfl_xor_sync(~0u, s, o);
    if (!lane) part[w] = s;
    __syncthreads();
    float tot = 0.f;
    #pragma unroll
    for (int i = 0; i < 8; i++) tot += part[i];
    float mean = tot * (1.0f / Cn);
    float d = v - mean;
    __syncthreads();

    s = d * d;
    #pragma unroll
    for (int o = 16; o; o >>= 1) s += __shfl_xor_sync(~0u, s, o);
    if (!lane) part[w] = s;
    __syncthreads();
    tot = 0.f;
    #pragma unroll
    for (int i = 0; i < 8; i++) tot += part[i];
    float var = tot * (1.0f / Cn);

    float r = d * rsqrtf(var + 1e-5f) * gg[c] + bb[c];
    out[token * Cn + c] = __float2half_rn(r);
}

// ---------------------------------------------------------------------------
// FP16 tensor-core GEMM (m16n8k16), cp.async 3-stage pipeline.
//   C[M,N] = A[M,K] @ Bt[N,K]^T ; A,Bt fp16, accum fp32.
//   EPI 0: plain   1: +bias   2: +bias,relu (half out)   3: +bias+residual
// Tile 128x128x32, 8 warps (2M x 4N), warp tile 64x32 (4x4 m16n8k16 atoms).
// Smem: padded stride 40 halves (20 words) -> conflict-free fragment LDS.
// ---------------------------------------------------------------------------
constexpr int TBM = 128;
constexpr int TBN = 128;
constexpr int TBK = 32;
constexpr int AS_H     = TBK + 8;                 // 40 halves per row
constexpr int A_BUF_H  = TBM * AS_H;              // 5120 halves
constexpr int B_BUF_H  = TBN * AS_H;              // 5120 halves
constexpr int STAGE_H  = A_BUF_H + B_BUF_H;       // 10240 halves = 20480 B
constexpr int STAGES   = 3;
constexpr int GEMM_SMEM_B = STAGES * STAGE_H * 2; // 61440 bytes -> 2 CTAs/SM

__device__ __forceinline__ void cp_async16(uint32_t daddr, const void* gptr,
                                           bool pred) {
    int sz = pred ? 16 : 0;
    asm volatile("cp.async.cg.shared.global [%0], [%1], 16, %2;\n"
                 :: "r"(daddr), "l"(gptr), "r"(sz));
}
__device__ __forceinline__ void cp_commit() {
    asm volatile("cp.async.commit_group;\n" ::: "memory");
}
template <int N>
__device__ __forceinline__ void cp_wait() {
    asm volatile("cp.async.wait_group %0;\n" :: "n"(N) : "memory");
}

__device__ __forceinline__ void mma_f16(float c[4], const uint32_t a[4],
                                        const uint32_t b[2]) {
    asm volatile(
        "mma.sync.aligned.m16n8k16.row.col.f32.f16.f16.f32 "
        "{%0,%1,%2,%3}, {%4,%5,%6,%7}, {%8,%9}, {%0,%1,%2,%3};"
        : "+f"(c[0]), "+f"(c[1]), "+f"(c[2]), "+f"(c[3])
        : "r"(a[0]), "r"(a[1]), "r"(a[2]), "r"(a[3]), "r"(b[0]), "r"(b[1]));
}

template <int EPI, bool OUT_HALF>
__global__ void __launch_bounds__(256, 2)
hgemm_kernel(const __half* __restrict__ A, const __half* __restrict__ Bt,
             const float* __restrict__ bias, const float* __restrict__ res,
             void* __restrict__ Cv, int M, int N, int K) {
    extern __shared__ __align__(16) uint8_t smem[];
    const uint32_t sbase = (uint32_t)__cvta_generic_to_shared(smem);
    const uint32_t* smem_w = reinterpret_cast<const uint32_t*>(smem);

    const int tid  = threadIdx.x;
    const int warp = tid >> 5;
    const int lane = tid & 31;
    const int wm   = warp & 1;          // 0..1 (M)
    const int wn   = warp >> 1;         // 0..3 (N)
    const int grp  = lane >> 2;         // 0..7
    const int qid  = lane & 3;          // 0..3
    const int rowBase = blockIdx.y * TBM;
    const int colBase = blockIdx.x * TBN;

    // per-thread copy coordinates: 512 16B-chunks each for A and B, 2/thread
    int cr[2], cu[2];
    bool b_ok[2];
    #pragma unroll
    for (int i = 0; i < 2; i++) {
        int f = tid + i * 256;
        cr[i] = f >> 2;                 // 0..127 (row / n-row)
        cu[i] = f & 3;                  // 16B chunk (8 halves)
        b_ok[i] = (colBase + cr[i]) < N;
    }

    auto issue = [&](int kt) {
        int st = kt % STAGES;
        uint32_t sa = sbase + st * STAGE_H * 2;
        uint32_t sb = sa + A_BUF_H * 2;
        #pragma unroll
        for (int i = 0; i < 2; i++) {
            const __half* g = A + (size_t)(rowBase + cr[i]) * K + kt * TBK + cu[i] * 8;
            cp_async16(sa + (cr[i] * AS_H + cu[i] * 8) * 2, g, true);
        }
        #pragma unroll
        for (int i = 0; i < 2; i++) {
            const __half* g = Bt + (size_t)(colBase + cr[i]) * K + kt * TBK + cu[i] * 8;
            cp_async16(sb + (cr[i] * AS_H + cu[i] * 8) * 2, g, b_ok[i]);
        }
        cp_commit();
    };

    float acc[4][4][4];
    #pragma unroll
    for (int i = 0; i < 4; i++)
        #pragma unroll
        for (int j = 0; j < 4; j++)
            #pragma unroll
            for (int r = 0; r < 4; r++) acc[i][j][r] = 0.0f;

    auto compute = [&](int st) {
        const uint32_t* Ab = smem_w + st * (STAGE_H / 2);
        const uint32_t* Bb = Ab + A_BUF_H / 2;
        #pragma unroll
        for (int ks = 0; ks < 2; ks++) {
            const int kw = ks * 8;              // k-offset in words
            uint32_t af[4][4], bf[4][2];
            #pragma unroll
            for (int ma = 0; ma < 4; ma++) {
                int m0 = wm * 64 + ma * 16 + grp;
                int base = m0 * (AS_H / 2) + kw + qid;
                af[ma][0] = Ab[base];
                af[ma][1] = Ab[base + 8 * (AS_H / 2)];
                af[ma][2] = Ab[base + 4];
                af[ma][3] = Ab[base + 8 * (AS_H / 2) + 4];
            }
            #pragma unroll
            for (int nb = 0; nb < 4; nb++) {
                int n0 = wn * 32 + nb * 8 + grp;
                int base = n0 * (AS_H / 2) + kw + qid;
                bf[nb][0] = Bb[base];
                bf[nb][1] = Bb[base + 4];
            }
            #pragma unroll
            for (int ma = 0; ma < 4; ma++)
                #pragma unroll
                for (int nb = 0; nb < 4; nb++)
                    mma_f16(acc[ma][nb], af[ma], bf[nb]);
        }
    };

    const int ktiles = K / TBK;
    issue(0);
    if (ktiles > 1) issue(1); else cp_commit();

    for (int kt = 0; kt < ktiles; kt++) {
        cp_wait<1>();
        __syncthreads();
        int nk = kt + 2;
        if (nk < ktiles) issue(nk); else cp_commit();
        compute(kt % STAGES);
        __syncthreads();
    }

    // ---- epilogue
    float*  Cf = reinterpret_cast<float*>(Cv);
    __half* Ch = reinterpret_cast<__half*>(Cv);
    #pragma unroll
    for (int ma = 0; ma < 4; ma++) {
        int row0 = rowBase + wm * 64 + ma * 16 + grp;
        #pragma unroll
        for (int nb = 0; nb < 4; nb++) {
            int col0 = colBase + wn * 32 + nb * 8 + qid * 2;
            #pragma unroll
            for (int half_i = 0; half_i < 2; half_i++) {
                int row = row0 + half_i * 8;
                #pragma unroll
                for (int j = 0; j < 2; j++) {
                    int col = col0 + j;
                    if (col < N) {
                        float v = acc[ma][nb][half_i * 2 + j];
                        if (EPI >= 1) v += bias[col];
                        if (EPI == 3) v += res[(size_t)row * N + col];
                        if (EPI == 2) v = fmaxf(v, 0.0f);
                        if (OUT_HALF) Ch[(size_t)row * N + col] = __float2half_rn(v);
                        else          Cf[(size_t)row * N + col] = v;
                    }
                }
            }
        }
    }
}

// ---------------------------------------------------------------------------
// Fused causal attention on packed qkv [NTOK][768] (fp32 in, fp16 out).
// One block per (head,batch), one thread per query, online softmax.
// scale = C^-0.5 = 1/16.
// ---------------------------------------------------------------------------
__global__ void __launch_bounds__(128)
attn_kernel(const float* __restrict__ qkv, __half* __restrict__ out) {
    __shared__ __align__(16) float Ks[64 * HSn];
    __shared__ __align__(16) float Vs[64 * HSn];

    const int h  = blockIdx.x;
    const int b  = blockIdx.y;
    const int tq = threadIdx.x;
    const int token = b * Tn + tq;

    float qr[HSn];
    #pragma unroll
    for (int d = 0; d < HSn; d += 4) {
        float4 t4 = *reinterpret_cast<const float4*>(
            &qkv[(size_t)token * QKVN + h * HSn + d]);
        qr[d] = t4.x; qr[d + 1] = t4.y; qr[d + 2] = t4.z; qr[d + 3] = t4.w;
    }

    float m = -1e30f, l = 0.0f;
    float acc[HSn];
    #pragma unroll
    for (int d = 0; d < HSn; d++) acc[d] = 0.0f;

    const int r    = tq >> 1;
    const int half = (tq & 1) * 32;

    for (int ch = 0; ch < 2; ch++) {
        __syncthreads();
        int tok2 = b * Tn + ch * 64 + r;
        #pragma unroll
        for (int d = 0; d < 32; d += 4) {
            int col = half + d;
            *reinterpret_cast<float4*>(&Ks[r * HSn + col]) =
                *reinterpret_cast<const float4*>(
                    &qkv[(size_t)tok2 * QKVN + Cn + h * HSn + col]);
            *reinterpret_cast<float4*>(&Vs[r * HSn + col]) =
                *reinterpret_cast<const float4*>(
                    &qkv[(size_t)tok2 * QKVN + 2 * Cn + h * HSn + col]);
        }
        __syncthreads();

        int tmax = tq - ch * 64;
        int lim  = tmax < 63 ? tmax : 63;
        for (int t = 0; t <= lim; t++) {
            float s = 0.0f;
            #pragma unroll
            for (int d = 0; d < HSn; d++) s = fmaf(qr[d], Ks[t * HSn + d], s);
            s *= 0.0625f;
            float mn   = fmaxf(m, s);
            float corr = __expf(m - mn);
            float p    = __expf(s - mn);
            l = l * corr + p;
            #pragma unroll
            for (int d = 0; d < HSn; d++)
                acc[d] = fmaf(acc[d], corr, p * Vs[t * HSn + d]);
            m = mn;
        }
    }

    float inv = 1.0f / l;
    #pragma unroll
    for (int d = 0; d < HSn; d++)
        out[(size_t)token * Cn + h * HSn + d] = __float2half_rn(acc[d] * inv);
}

// ---------------------------------------------------------------------------
// Host driver (graph-capturable)
// ---------------------------------------------------------------------------
extern "C" void kernel_launch(void* const* d_in, const int* in_sizes, int n_in,
                              void* d_out, int out_size) {
    const int*   idx     = (const int*)  d_in[0];
    const float* tok_emb = (const float*)d_in[1];
    const float* pos_emb = (const float*)d_in[2];
    const float* ln1_g   = (const float*)d_in[3];
    const float* ln1_b   = (const float*)d_in[4];
    const float* wq      = (const float*)d_in[5];
    const float* wk      = (const float*)d_in[6];
    const float* wv      = (const float*)d_in[7];
    const float* proj_w  = (const float*)d_in[8];
    const float* proj_b  = (const float*)d_in[9];
    const float* ln2_g   = (const float*)d_in[10];
    const float* ln2_b   = (const float*)d_in[11];
    const float* w1      = (const float*)d_in[12];
    const float* b1      = (const float*)d_in[13];
    const float* w2      = (const float*)d_in[14];
    const float* b2      = (const float*)d_in[15];
    const float* lnf_g   = (const float*)d_in[16];
    const float* lnf_b   = (const float*)d_in[17];
    const float* lm_w    = (const float*)d_in[18];
    const float* lm_b    = (const float*)d_in[19];
    float*       out     = (float*)d_out;

    float  *x, *qkvb;
    __half *h, *att, *ffn, *qkvw, *projw, *w1t, *w2t, *lmt;
    cudaGetSymbolAddress((void**)&x,     g_x);
    cudaGetSymbolAddress((void**)&h,     g_h);
    cudaGetSymbolAddress((void**)&qkvb,  g_qkv);
    cudaGetSymbolAddress((void**)&att,   g_att);
    cudaGetSymbolAddress((void**)&ffn,   g_ffn);
    cudaGetSymbolAddress((void**)&qkvw,  g_qkvw);
    cudaGetSymbolAddress((void**)&projw, g_projw);
    cudaGetSymbolAddress((void**)&w1t,   g_w1);
    cudaGetSymbolAddress((void**)&w2t,   g_w2);
    cudaGetSymbolAddress((void**)&lmt,   g_lmw);

    cudaFuncSetAttribute(hgemm_kernel<0,false>, cudaFuncAttributeMaxDynamicSharedMemorySize, GEMM_SMEM_B);
    cudaFuncSetAttribute(hgemm_kernel<1,false>, cudaFuncAttributeMaxDynamicSharedMemorySize, GEMM_SMEM_B);
    cudaFuncSetAttribute(hgemm_kernel<2,true >, cudaFuncAttributeMaxDynamicSharedMemorySize, GEMM_SMEM_B);
    cudaFuncSetAttribute(hgemm_kernel<3,false>, cudaFuncAttributeMaxDynamicSharedMemorySize, GEMM_SMEM_B);

    // --- weight prepack: transpose + fp16 into [N,K] K-major scratch
    {
        dim3 thr(32, 8);
        trt_kernel<<<dim3(8, 8, Ln), thr>>>(wq, qkvw,               Cn, Cn,
                                            (size_t)Cn * Cn, (size_t)QKVN * Cn);
        trt_kernel<<<dim3(8, 8, Ln), thr>>>(wk, qkvw + Cn * Cn,     Cn, Cn,
                                            (size_t)Cn * Cn, (size_t)QKVN * Cn);
        trt_kernel<<<dim3(8, 8, Ln), thr>>>(wv, qkvw + 2 * Cn * Cn, Cn, Cn,
                                            (size_t)Cn * Cn, (size_t)QKVN * Cn);
        trt_kernel<<<dim3(8, 8, Ln), thr>>>(proj_w, projw,          Cn, Cn,
                                            (size_t)Cn * Cn, (size_t)Cn * Cn);
        trt_kernel<<<dim3(32, 8, Ln), thr>>>(w1, w1t,               Cn, DFFn,
                                            (size_t)Cn * DFFn, (size_t)Cn * DFFn);
        trt_kernel<<<dim3(8, 32, Ln), thr>>>(w2, w2t,               DFFn, Cn,
                                            (size_t)Cn * DFFn, (size_t)Cn * DFFn);
        trt_kernel<<<dim3(313, 8, 1), thr>>>(lm_w, lmt,             Cn, Vn,
                                            (size_t)Cn * Vn, (size_t)Cn * Vn);
    }

    embed_kernel<<<NTOK, Cn>>>(idx, tok_emb, pos_emb);

    dim3 gridQKV(QKVN / TBN,       NTOK / TBM);   // (6, 128)
    dim3 gridC  (Cn / TBN,         NTOK / TBM);   // (2, 128)
    dim3 gridF  (DFFn / TBN,       NTOK / TBM);   // (8, 128)
    dim3 gridV  ((Vn + TBN - 1) / TBN, NTOK / TBM);   // (79, 128)
    dim3 gridA  (Hn, Bn);

    for (int l = 0; l < Ln; l++) {
        const __half* Wqkv = qkvw  + (size_t)l * Cn * QKVN;
        const __half* Wp   = projw + (size_t)l * Cn * Cn;
        const __half* W1   = w1t   + (size_t)l * Cn * DFFn;
        const __half* W2   = w2t   + (size_t)l * DFFn * Cn;

        ln_kernel<<<NTOK, Cn>>>(x, ln1_g + l * Cn, ln1_b + l * Cn, h);

        hgemm_kernel<0,false><<<gridQKV, 256, GEMM_SMEM_B>>>(
            h, Wqkv, nullptr, nullptr, qkvb, NTOK, QKVN, Cn);

        attn_kernel<<<gridA, 128>>>(qkvb, att);

        hgemm_kernel<3,false><<<gridC, 256, GEMM_SMEM_B>>>(
            att, Wp, proj_b + l * Cn, x, x, NTOK, Cn, Cn);

        ln_kernel<<<NTOK, Cn>>>(x, ln2_g + l * Cn, ln2_b + l * Cn, h);

        hgemm_kernel<2,true><<<gridF, 256, GEMM_SMEM_B>>>(
            h, W1, b1 + l * DFFn, nullptr, ffn, NTOK, DFFn, Cn);
        hgemm_kernel<3,false><<<gridC, 256, GEMM_SMEM_B>>>(
            ffn, W2, b2 + l * Cn, x, x, NTOK, Cn, DFFn);
    }

    ln_kernel<<<NTOK, Cn>>>(x, lnf_g, lnf_b, h);
    hgemm_kernel<1,false><<<gridV, 256, GEMM_SMEM_B>>>(
        h, lmt, lm_b, nullptr, out, NTOK, Vn, Cn);
}

// round 11
// speedup vs baseline: 1.3733x; 1.3733x over previous
#include <cuda_runtime.h>
#include <cuda_fp16.h>
#include <cstdint>

// ---------------------------------------------------------------------------
// Problem constants
// ---------------------------------------------------------------------------
constexpr int Bn   = 128;
constexpr int Tn   = 128;
constexpr int Cn   = 256;
constexpr int Hn   = 4;
constexpr int Ln   = 6;
constexpr int Vn   = 10000;
constexpr int HSn  = 64;
constexpr int DFFn = 1024;
constexpr int NTOK = Bn * Tn;
constexpr int QKVN = 3 * Cn;       // 768

// ---------------------------------------------------------------------------
// Scratch (device globals -- allocation-free per harness rules)
// ---------------------------------------------------------------------------
__device__ float  g_x   [NTOK * Cn];      // residual stream (fp32)
__device__ __half g_h   [NTOK * Cn];      // LN output (fp16, GEMM A)
__device__ float  g_qkv [NTOK * QKVN];    // QKV GEMM out (fp32, attn input)
__device__ __half g_att [NTOK * Cn];      // attn output (fp16, GEMM A)
__device__ __half g_ffn [NTOK * DFFn];    // relu output (fp16, GEMM A)
// fp16, TRANSPOSED ([N,K] K-major) weight copies for GEMM B operand
__device__ __half g_qkvw[Ln * Cn * QKVN];
__device__ __half g_projw[Ln * Cn * Cn];
__device__ __half g_w1  [Ln * Cn * DFFn];
__device__ __half g_w2  [Ln * DFFn * Cn];
__device__ __half g_lmw [Cn * Vn];

// ---------------------------------------------------------------------------
// Fused prepack: transpose + fp16 convert for ALL weight tensors in ONE launch.
// Each 32x32 tile block is routed to its tensor via a job table.
// ---------------------------------------------------------------------------
struct TrtJob {
    const float* src;
    __half*      dst;
    int Ksz, Nsz, nx, ny;
    long long ss, ds;          // per-slice strides (elements)
    int base, count;
};
struct TrtPack { TrtJob j[7]; };

__global__ void trt_all(TrtPack p) {
    __shared__ float tile[32][33];
    int bid = blockIdx.x;
    #pragma unroll
    for (int t = 0; t < 7; t++) {
        const TrtJob J = p.j[t];
        if (bid >= J.base && bid < J.base + J.count) {
            int r  = bid - J.base;
            int bx = r % J.nx; r /= J.nx;
            int by = r % J.ny;
            int bz = r / J.ny;
            const float* s = J.src + (long long)bz * J.ss;
            __half*      d = J.dst + (long long)bz * J.ds;
            int k0 = by * 32, n0 = bx * 32;
            int tx = threadIdx.x, ty = threadIdx.y;     // 32 x 8
            #pragma unroll
            for (int jj = 0; jj < 32; jj += 8) {
                int k = k0 + ty + jj, n = n0 + tx;
                if (k < J.Ksz && n < J.Nsz)
                    tile[ty + jj][tx] = s[(size_t)k * J.Nsz + n];
            }
            __syncthreads();
            #pragma unroll
            for (int jj = 0; jj < 32; jj += 8) {
                int n = n0 + ty + jj, k = k0 + tx;
                if (n < J.Nsz && k < J.Ksz)
                    d[(size_t)n * J.Ksz + k] = __float2half_rn(tile[tx][ty + jj]);
            }
            return;
        }
    }
}

// ---------------------------------------------------------------------------
// Embedding
// ---------------------------------------------------------------------------
__global__ void embed_kernel(const int* __restrict__ idx,
                             const float* __restrict__ tok,
                             const float* __restrict__ pos) {
    int token = blockIdx.x;
    int c     = threadIdx.x;
    int t     = token % Tn;
    int id    = idx[token];
    g_x[token * Cn + c] = tok[id * Cn + c] + pos[t * Cn + c];
}

// ---------------------------------------------------------------------------
// LayerNorm (shuffle reductions), fp16 output (feeds GEMM A operand)
// ---------------------------------------------------------------------------
__global__ void __launch_bounds__(Cn)
ln_kernel(const float* __restrict__ in, const float* __restrict__ gg,
          const float* __restrict__ bb, __half* __restrict__ out) {
    __shared__ float part[8];
    int token = blockIdx.x;
    int c     = threadIdx.x;
    int lane  = c & 31, w = c >> 5;
    float v = in[token * Cn + c];

    float s = v;
    #pragma unroll
    for (int o = 16; o; o >>= 1) s += __shfl_xor_sync(~0u, s, o);
    if (!lane) part[w] = s;
    __syncthreads();
    float tot = 0.f;
    #pragma unroll
    for (int i = 0; i < 8; i++) tot += part[i];
    float mean = tot * (1.0f / Cn);
    float d = v - mean;
    __syncthreads();

    s = d * d;
    #pragma unroll
    for (int o = 16; o; o >>= 1) s += __shfl_xor_sync(~0u, s, o);
    if (!lane) part[w] = s;
    __syncthreads();
    tot = 0.f;
    #pragma unroll
    for (int i = 0; i < 8; i++) tot += part[i];
    float var = tot * (1.0f / Cn);

    float r = d * rsqrtf(var + 1e-5f) * gg[c] + bb[c];
    out[token * Cn + c] = __float2half_rn(r);
}

// ---------------------------------------------------------------------------
// FP16 tensor-core GEMM (m16n8k16), cp.async 3-stage pipeline, 512 threads.
//   C[M,N] = A[M,K] @ Bt[N,K]^T ; A,Bt fp16, accum fp32.
//   EPI 0: plain   1: +bias   2: +bias,relu (half out)   3: +bias+residual
// Tile 128x128x32, 16 warps (4M x 4N), warp tile 32x32 (2x4 m16n8k16 atoms).
// acc = 32 regs/thread -> ~100 regs total, no spill, 16 warps resident.
// Smem: padded stride 40 halves -> conflict-free fragment LDS
// (bank = grp*20+qid mod 32 is a bijection over the warp).
// ---------------------------------------------------------------------------
constexpr int TBM = 128;
constexpr int TBN = 128;
constexpr int TBK = 32;
constexpr int AS_H     = TBK + 8;                 // 40 halves per row
constexpr int A_BUF_H  = TBM * AS_H;              // 5120 halves
constexpr int B_BUF_H  = TBN * AS_H;              // 5120 halves
constexpr int STAGE_H  = A_BUF_H + B_BUF_H;       // 10240 halves = 20480 B
constexpr int STAGES   = 3;
constexpr int GEMM_SMEM_B = STAGES * STAGE_H * 2; // 61440 bytes

__device__ __forceinline__ void cp_async16(uint32_t daddr, const void* gptr,
                                           bool pred) {
    int sz = pred ? 16 : 0;
    asm volatile("cp.async.cg.shared.global [%0], [%1], 16, %2;\n"
                 :: "r"(daddr), "l"(gptr), "r"(sz));
}
__device__ __forceinline__ void cp_commit() {
    asm volatile("cp.async.commit_group;\n" ::: "memory");
}
template <int N>
__device__ __forceinline__ void cp_wait() {
    asm volatile("cp.async.wait_group %0;\n" :: "n"(N) : "memory");
}

__device__ __forceinline__ void mma_f16(float c[4], const uint32_t a[4],
                                        const uint32_t b[2]) {
    asm volatile(
        "mma.sync.aligned.m16n8k16.row.col.f32.f16.f16.f32 "
        "{%0,%1,%2,%3}, {%4,%5,%6,%7}, {%8,%9}, {%0,%1,%2,%3};"
        : "+f"(c[0]), "+f"(c[1]), "+f"(c[2]), "+f"(c[3])
        : "r"(a[0]), "r"(a[1]), "r"(a[2]), "r"(a[3]), "r"(b[0]), "r"(b[1]));
}

template <int EPI, bool OUT_HALF>
__global__ void __launch_bounds__(512, 1)
hgemm_kernel(const __half* __restrict__ A, const __half* __restrict__ Bt,
             const float* __restrict__ bias, const float* __restrict__ res,
             void* __restrict__ Cv, int M, int N, int K) {
    extern __shared__ __align__(16) uint8_t smem[];
    const uint32_t sbase = (uint32_t)__cvta_generic_to_shared(smem);
    const uint32_t* smem_w = reinterpret_cast<const uint32_t*>(smem);

    const int tid  = threadIdx.x;
    const int warp = tid >> 5;
    const int lane = tid & 31;
    const int wm   = warp & 3;          // 0..3 (M)
    const int wn   = warp >> 2;         // 0..3 (N)
    const int grp  = lane >> 2;         // 0..7
    const int qid  = lane & 3;          // 0..3
    const int rowBase = blockIdx.y * TBM;
    const int colBase = blockIdx.x * TBN;

    // loader: 512 16B-chunks for A, 512 for B; exactly 1 each per thread
    const int cr = tid >> 2;            // 0..127 (A row / B n-row)
    const int cu = tid & 3;             // 16B chunk (8 halves)
    const bool b_ok = (colBase + cr) < N;

    auto issue = [&](int kt) {
        int st = kt % STAGES;
        uint32_t sa = sbase + st * STAGE_H * 2;
        uint32_t sb = sa + A_BUF_H * 2;
        const __half* ga = A + (size_t)(rowBase + cr) * K + kt * TBK + cu * 8;
        cp_async16(sa + (cr * AS_H + cu * 8) * 2, ga, true);
        const __half* gb = Bt + (size_t)(colBase + cr) * K + kt * TBK + cu * 8;
        cp_async16(sb + (cr * AS_H + cu * 8) * 2, gb, b_ok);
        cp_commit();
    };

    float acc[2][4][4];
    #pragma unroll
    for (int i = 0; i < 2; i++)
        #pragma unroll
        for (int j = 0; j < 4; j++)
            #pragma unroll
            for (int r = 0; r < 4; r++) acc[i][j][r] = 0.0f;

    auto compute = [&](int st) {
        const uint32_t* Ab = smem_w + st * (STAGE_H / 2);
        const uint32_t* Bb = Ab + A_BUF_H / 2;
        #pragma unroll
        for (int ks = 0; ks < 2; ks++) {
            const int kw = ks * 8;              // k-offset in words
            uint32_t af[2][4], bf[4][2];
            #pragma unroll
            for (int ma = 0; ma < 2; ma++) {
                int m0 = wm * 32 + ma * 16 + grp;
                int base = m0 * (AS_H / 2) + kw + qid;
                af[ma][0] = Ab[base];
                af[ma][1] = Ab[base + 8 * (AS_H / 2)];
                af[ma][2] = Ab[base + 4];
                af[ma][3] = Ab[base + 8 * (AS_H / 2) + 4];
            }
            #pragma unroll
            for (int nb = 0; nb < 4; nb++) {
                int n0 = wn * 32 + nb * 8 + grp;
                int base = n0 * (AS_H / 2) + kw + qid;
                bf[nb][0] = Bb[base];
                bf[nb][1] = Bb[base + 4];
            }
            #pragma unroll
            for (int ma = 0; ma < 2; ma++)
                #pragma unroll
                for (int nb = 0; nb < 4; nb++)
                    mma_f16(acc[ma][nb], af[ma], bf[nb]);
        }
    };

    const int ktiles = K / TBK;
    issue(0);
    if (ktiles > 1) issue(1); else cp_commit();

    for (int kt = 0; kt < ktiles; kt++) {
        cp_wait<1>();
        __syncthreads();
        int nk = kt + 2;
        if (nk < ktiles) issue(nk); else cp_commit();
        compute(kt % STAGES);
        __syncthreads();
    }

    // ---- epilogue
    float*  Cf = reinterpret_cast<float*>(Cv);
    __half* Ch = reinterpret_cast<__half*>(Cv);
    #pragma unroll
    for (int ma = 0; ma < 2; ma++) {
        int row0 = rowBase + wm * 32 + ma * 16 + grp;
        #pragma unroll
        for (int nb = 0; nb < 4; nb++) {
            int col0 = colBase + wn * 32 + nb * 8 + qid * 2;
            #pragma unroll
            for (int half_i = 0; half_i < 2; half_i++) {
                int row = row0 + half_i * 8;
                #pragma unroll
                for (int j = 0; j < 2; j++) {
                    int col = col0 + j;
                    if (col < N) {
                        float v = acc[ma][nb][half_i * 2 + j];
                        if (EPI >= 1) v += bias[col];
                        if (EPI == 3) v += res[(size_t)row * N + col];
                        if (EPI == 2) v = fmaxf(v, 0.0f);
                        if (OUT_HALF) Ch[(size_t)row * N + col] = __float2half_rn(v);
                        else          Cf[(size_t)row * N + col] = v;
                    }
                }
            }
        }
    }
}

// ---------------------------------------------------------------------------
// Fused causal attention on packed qkv [NTOK][768] (fp32 in, fp16 out).
// One block per (head,batch), one thread per query, online softmax.
// scale = C^-0.5 = 1/16.
// ---------------------------------------------------------------------------
__global__ void __launch_bounds__(128)
attn_kernel(const float* __restrict__ qkv, __half* __restrict__ out) {
    __shared__ __align__(16) float Ks[64 * HSn];
    __shared__ __align__(16) float Vs[64 * HSn];

    const int h  = blockIdx.x;
    const int b  = blockIdx.y;
    const int tq = threadIdx.x;
    const int token = b * Tn + tq;

    float qr[HSn];
    #pragma unroll
    for (int d = 0; d < HSn; d += 4) {
        float4 t4 = *reinterpret_cast<const float4*>(
            &qkv[(size_t)token * QKVN + h * HSn + d]);
        qr[d] = t4.x; qr[d + 1] = t4.y; qr[d + 2] = t4.z; qr[d + 3] = t4.w;
    }

    float m = -1e30f, l = 0.0f;
    float acc[HSn];
    #pragma unroll
    for (int d = 0; d < HSn; d++) acc[d] = 0.0f;

    const int r    = tq >> 1;
    const int half = (tq & 1) * 32;

    for (int ch = 0; ch < 2; ch++) {
        __syncthreads();
        int tok2 = b * Tn + ch * 64 + r;
        #pragma unroll
        for (int d = 0; d < 32; d += 4) {
            int col = half + d;
            *reinterpret_cast<float4*>(&Ks[r * HSn + col]) =
                *reinterpret_cast<const float4*>(
                    &qkv[(size_t)tok2 * QKVN + Cn + h * HSn + col]);
            *reinterpret_cast<float4*>(&Vs[r * HSn + col]) =
                *reinterpret_cast<const float4*>(
                    &qkv[(size_t)tok2 * QKVN + 2 * Cn + h * HSn + col]);
        }
        __syncthreads();

        int tmax = tq - ch * 64;
        int lim  = tmax < 63 ? tmax : 63;
        for (int t = 0; t <= lim; t++) {
            float s = 0.0f;
            #pragma unroll
            for (int d = 0; d < HSn; d++) s = fmaf(qr[d], Ks[t * HSn + d], s);
            s *= 0.0625f;
            float mn   = fmaxf(m, s);
            float corr = __expf(m - mn);
            float p    = __expf(s - mn);
            l = l * corr + p;
            #pragma unroll
            for (int d = 0; d < HSn; d++)
                acc[d] = fmaf(acc[d], corr, p * Vs[t * HSn + d]);
            m = mn;
        }
    }

    float inv = 1.0f / l;
    #pragma unroll
    for (int d = 0; d < HSn; d++)
        out[(size_t)token * Cn + h * HSn + d] = __float2half_rn(acc[d] * inv);
}

// ---------------------------------------------------------------------------
// Host driver (graph-capturable)
// ---------------------------------------------------------------------------
extern "C" void kernel_launch(void* const* d_in, const int* in_sizes, int n_in,
                              void* d_out, int out_size) {
    const int*   idx     = (const int*)  d_in[0];
    const float* tok_emb = (const float*)d_in[1];
    const float* pos_emb = (const float*)d_in[2];
    const float* ln1_g   = (const float*)d_in[3];
    const float* ln1_b   = (const float*)d_in[4];
    const float* wq      = (const float*)d_in[5];
    const float* wk      = (const float*)d_in[6];
    const float* wv      = (const float*)d_in[7];
    const float* proj_w  = (const float*)d_in[8];
    const float* proj_b  = (const float*)d_in[9];
    const float* ln2_g   = (const float*)d_in[10];
    const float* ln2_b   = (const float*)d_in[11];
    const float* w1      = (const float*)d_in[12];
    const float* b1      = (const float*)d_in[13];
    const float* w2      = (const float*)d_in[14];
    const float* b2      = (const float*)d_in[15];
    const float* lnf_g   = (const float*)d_in[16];
    const float* lnf_b   = (const float*)d_in[17];
    const float* lm_w    = (const float*)d_in[18];
    const float* lm_b    = (const float*)d_in[19];
    float*       out     = (float*)d_out;

    float  *x, *qkvb;
    __half *h, *att, *ffn, *qkvw, *projw, *w1t, *w2t, *lmt;
    cudaGetSymbolAddress((void**)&x,     g_x);
    cudaGetSymbolAddress((void**)&h,     g_h);
    cudaGetSymbolAddress((void**)&qkvb,  g_qkv);
    cudaGetSymbolAddress((void**)&att,   g_att);
    cudaGetSymbolAddress((void**)&ffn,   g_ffn);
    cudaGetSymbolAddress((void**)&qkvw,  g_qkvw);
    cudaGetSymbolAddress((void**)&projw, g_projw);
    cudaGetSymbolAddress((void**)&w1t,   g_w1);
    cudaGetSymbolAddress((void**)&w2t,   g_w2);
    cudaGetSymbolAddress((void**)&lmt,   g_lmw);

    cudaFuncSetAttribute(hgemm_kernel<0,false>, cudaFuncAttributeMaxDynamicSharedMemorySize, GEMM_SMEM_B);
    cudaFuncSetAttribute(hgemm_kernel<1,false>, cudaFuncAttributeMaxDynamicSharedMemorySize, GEMM_SMEM_B);
    cudaFuncSetAttribute(hgemm_kernel<2,true >, cudaFuncAttributeMaxDynamicSharedMemorySize, GEMM_SMEM_B);
    cudaFuncSetAttribute(hgemm_kernel<3,false>, cudaFuncAttributeMaxDynamicSharedMemorySize, GEMM_SMEM_B);

    // --- fused weight prepack (single launch)
    {
        TrtPack p;
        int base = 0;
        auto mk = [&](const float* s, __half* d, int K, int N, int nz,
                      long long ss, long long ds) {
            int nx = (N + 31) / 32, ny = (K + 31) / 32;
            TrtJob J{s, d, K, N, nx, ny, ss, ds, base, nx * ny * nz};
            base += J.count;
            return J;
        };
        p.j[0] = mk(wq,     qkvw,               Cn, Cn,  Ln, (long long)Cn * Cn,   (long long)QKVN * Cn);
        p.j[1] = mk(wk,     qkvw + Cn * Cn,     Cn, Cn,  Ln, (long long)Cn * Cn,   (long long)QKVN * Cn);
        p.j[2] = mk(wv,     qkvw + 2 * Cn * Cn, Cn, Cn,  Ln, (long long)Cn * Cn,   (long long)QKVN * Cn);
        p.j[3] = mk(proj_w, projw,              Cn, Cn,  Ln, (long long)Cn * Cn,   (long long)Cn * Cn);
        p.j[4] = mk(w1,     w1t,                Cn, DFFn, Ln, (long long)Cn * DFFn, (long long)Cn * DFFn);
        p.j[5] = mk(w2,     w2t,                DFFn, Cn, Ln, (long long)Cn * DFFn, (long long)Cn * DFFn);
        p.j[6] = mk(lm_w,   lmt,                Cn, Vn,  1,  (long long)Cn * Vn,   (long long)Cn * Vn);
        trt_all<<<base, dim3(32, 8)>>>(p);
    }

    embed_kernel<<<NTOK, Cn>>>(idx, tok_emb, pos_emb);

    dim3 gridQKV(QKVN / TBN,           NTOK / TBM);   // (6, 128)
    dim3 gridC  (Cn / TBN,             NTOK / TBM);   // (2, 128)
    dim3 gridF  (DFFn / TBN,           NTOK / TBM);   // (8, 128)
    dim3 gridV  ((Vn + TBN - 1) / TBN, NTOK / TBM);   // (79, 128)
    dim3 gridA  (Hn, Bn);

    for (int l = 0; l < Ln; l++) {
        const __half* Wqkv = qkvw  + (size_t)l * Cn * QKVN;
        const __half* Wp   = projw + (size_t)l * Cn * Cn;
        const __half* W1   = w1t   + (size_t)l * Cn * DFFn;
        const __half* W2   = w2t   + (size_t)l * DFFn * Cn;

        ln_kernel<<<NTOK, Cn>>>(x, ln1_g + l * Cn, ln1_b + l * Cn, h);

        hgemm_kernel<0,false><<<gridQKV, 512, GEMM_SMEM_B>>>(
            h, Wqkv, nullptr, nullptr, qkvb, NTOK, QKVN, Cn);

        attn_kernel<<<gridA, 128>>>(qkvb, att);

        hgemm_kernel<3,false><<<gridC, 512, GEMM_SMEM_B>>>(
            att, Wp, proj_b + l * Cn, x, x, NTOK, Cn, Cn);

        ln_kernel<<<NTOK, Cn>>>(x, ln2_g + l * Cn, ln2_b + l * Cn, h);

        hgemm_kernel<2,true><<<gridF, 512, GEMM_SMEM_B>>>(
            h, W1, b1 + l * DFFn, nullptr, ffn, NTOK, DFFn, Cn);
        hgemm_kernel<3,false><<<gridC, 512, GEMM_SMEM_B>>>(
            ffn, W2, b2 + l * Cn, x, x, NTOK, Cn, DFFn);
    }

    ln_kernel<<<NTOK, Cn>>>(x, lnf_g, lnf_b, h);
    hgemm_kernel<1,false><<<gridV, 512, GEMM_SMEM_B>>>(
        h, lmt, lm_b, nullptr, out, NTOK, Vn, Cn);
}

// round 13
// speedup vs baseline: 1.5866x; 1.1553x over previous
#include <cuda_runtime.h>
#include <cuda_fp16.h>
#include <cstdint>

// ---------------------------------------------------------------------------
// Problem constants
// ---------------------------------------------------------------------------
constexpr int Bn   = 128;
constexpr int Tn   = 128;
constexpr int Cn   = 256;
constexpr int Hn   = 4;
constexpr int Ln   = 6;
constexpr int Vn   = 10000;
constexpr int HSn  = 64;
constexpr int DFFn = 1024;
constexpr int NTOK = Bn * Tn;
constexpr int QKVN = 3 * Cn;       // 768

// ---------------------------------------------------------------------------
// Scratch (device globals -- allocation-free per harness rules)
// ---------------------------------------------------------------------------
__device__ float  g_x   [NTOK * Cn];      // residual stream (fp32)
__device__ __half g_h   [NTOK * Cn];      // LN output (fp16, GEMM A)
__device__ float  g_qkv [NTOK * QKVN];    // QKV GEMM out (fp32, attn input)
__device__ __half g_att [NTOK * Cn];      // attn output (fp16, GEMM A)
__device__ __half g_ffn [NTOK * DFFn];    // relu output (fp16, GEMM A)
// fp16, TRANSPOSED ([N,K] K-major) weight copies for GEMM B operand
__device__ __half g_qkvw[Ln * Cn * QKVN];
__device__ __half g_projw[Ln * Cn * Cn];
__device__ __half g_w1  [Ln * Cn * DFFn];
__device__ __half g_w2  [Ln * DFFn * Cn];
__device__ __half g_lmw [Cn * Vn];

// ---------------------------------------------------------------------------
// Fused prepack: transpose + fp16 convert, one launch for all weights.
// ---------------------------------------------------------------------------
struct TrtJob {
    const float* src;
    __half*      dst;
    int Ksz, Nsz, nx, ny;
    long long ss, ds;
    int base, count;
};
struct TrtPack { TrtJob j[7]; };

__global__ void trt_all(TrtPack p) {
    __shared__ float tile[32][33];
    int bid = blockIdx.x;
    #pragma unroll
    for (int t = 0; t < 7; t++) {
        const TrtJob J = p.j[t];
        if (bid >= J.base && bid < J.base + J.count) {
            int r  = bid - J.base;
            int bx = r % J.nx; r /= J.nx;
            int by = r % J.ny;
            int bz = r / J.ny;
            const float* s = J.src + (long long)bz * J.ss;
            __half*      d = J.dst + (long long)bz * J.ds;
            int k0 = by * 32, n0 = bx * 32;
            int tx = threadIdx.x, ty = threadIdx.y;
            #pragma unroll
            for (int jj = 0; jj < 32; jj += 8) {
                int k = k0 + ty + jj, n = n0 + tx;
                if (k < J.Ksz && n < J.Nsz)
                    tile[ty + jj][tx] = s[(size_t)k * J.Nsz + n];
            }
            __syncthreads();
            #pragma unroll
            for (int jj = 0; jj < 32; jj += 8) {
                int n = n0 + ty + jj, k = k0 + tx;
                if (n < J.Nsz && k < J.Ksz)
                    d[(size_t)n * J.Ksz + k] = __float2half_rn(tile[tx][ty + jj]);
            }
            return;
        }
    }
}

// ---------------------------------------------------------------------------
// Embedding
// ---------------------------------------------------------------------------
__global__ void embed_kernel(const int* __restrict__ idx,
                             const float* __restrict__ tok,
                             const float* __restrict__ pos) {
    int token = blockIdx.x;
    int c     = threadIdx.x;
    int t     = token % Tn;
    int id    = idx[token];
    g_x[token * Cn + c] = tok[id * Cn + c] + pos[t * Cn + c];
}

// ---------------------------------------------------------------------------
// LayerNorm (shuffle reductions), fp16 output
// ---------------------------------------------------------------------------
__global__ void __launch_bounds__(Cn)
ln_kernel(const float* __restrict__ in, const float* __restrict__ gg,
          const float* __restrict__ bb, __half* __restrict__ out) {
    __shared__ float part[8];
    int token = blockIdx.x;
    int c     = threadIdx.x;
    int lane  = c & 31, w = c >> 5;
    float v = in[token * Cn + c];

    float s = v;
    #pragma unroll
    for (int o = 16; o; o >>= 1) s += __shfl_xor_sync(~0u, s, o);
    if (!lane) part[w] = s;
    __syncthreads();
    float tot = 0.f;
    #pragma unroll
    for (int i = 0; i < 8; i++) tot += part[i];
    float mean = tot * (1.0f / Cn);
    float d = v - mean;
    __syncthreads();

    s = d * d;
    #pragma unroll
    for (int o = 16; o; o >>= 1) s += __shfl_xor_sync(~0u, s, o);
    if (!lane) part[w] = s;
    __syncthreads();
    tot = 0.f;
    #pragma unroll
    for (int i = 0; i < 8; i++) tot += part[i];
    float var = tot * (1.0f / Cn);

    float r = d * rsqrtf(var + 1e-5f) * gg[c] + bb[c];
    out[token * Cn + c] = __float2half_rn(r);
}

// ---------------------------------------------------------------------------
// FP16 tensor-core GEMM (m16n8k16) with ldmatrix fragment loads.
// 4-stage cp.async ring, ONE __syncthreads per ktile.
// Tile 128x128x32, 16 warps (4M x 4N), warp tile 32x32.
// ---------------------------------------------------------------------------
constexpr int TBM = 128;
constexpr int TBN = 128;
constexpr int TBK = 32;
constexpr int AS_H     = TBK + 8;                 // 40 halves per row
constexpr int A_BUF_H  = TBM * AS_H;              // 5120 halves
constexpr int B_BUF_H  = TBN * AS_H;              // 5120 halves
constexpr int STAGE_H  = A_BUF_H + B_BUF_H;       // 10240 halves = 20480 B
constexpr int STAGES   = 4;
constexpr int GEMM_SMEM_B = STAGES * STAGE_H * 2; // 81920 bytes

__device__ __forceinline__ void cp_async16(uint32_t daddr, const void* gptr,
                                           bool pred) {
    int sz = pred ? 16 : 0;
    asm volatile("cp.async.cg.shared.global [%0], [%1], 16, %2;\n"
                 :: "r"(daddr), "l"(gptr), "r"(sz));
}
__device__ __forceinline__ void cp_commit() {
    asm volatile("cp.async.commit_group;\n" ::: "memory");
}
template <int N>
__device__ __forceinline__ void cp_wait() {
    asm volatile("cp.async.wait_group %0;\n" :: "n"(N) : "memory");
}
__device__ __forceinline__ void ldsm4(uint32_t r[4], uint32_t addr) {
    asm volatile("ldmatrix.sync.aligned.m8n8.x4.shared.b16 {%0,%1,%2,%3}, [%4];"
                 : "=r"(r[0]), "=r"(r[1]), "=r"(r[2]), "=r"(r[3]) : "r"(addr));
}
__device__ __forceinline__ void mma_f16(float c[4], const uint32_t a[4],
                                        const uint32_t b[2]) {
    asm volatile(
        "mma.sync.aligned.m16n8k16.row.col.f32.f16.f16.f32 "
        "{%0,%1,%2,%3}, {%4,%5,%6,%7}, {%8,%9}, {%0,%1,%2,%3};"
        : "+f"(c[0]), "+f"(c[1]), "+f"(c[2]), "+f"(c[3])
        : "r"(a[0]), "r"(a[1]), "r"(a[2]), "r"(a[3]), "r"(b[0]), "r"(b[1]));
}

template <int EPI, bool OUT_HALF>
__global__ void __launch_bounds__(512, 1)
hgemm_kernel(const __half* __restrict__ A, const __half* __restrict__ Bt,
             const float* __restrict__ bias, const float* __restrict__ res,
             void* __restrict__ Cv, int M, int N, int K) {
    extern __shared__ __align__(16) uint8_t smem[];
    const uint32_t sbase = (uint32_t)__cvta_generic_to_shared(smem);

    const int tid  = threadIdx.x;
    const int warp = tid >> 5;
    const int lane = tid & 31;
    const int wm   = warp & 3;          // 0..3 (M)
    const int wn   = warp >> 2;         // 0..3 (N)
    const int grp  = lane >> 2;
    const int qid  = lane & 3;
    const int rowBase = blockIdx.y * TBM;
    const int colBase = blockIdx.x * TBN;

    // ldmatrix per-lane byte offsets within a stage (A at 0, B at A_BUF_H*2)
    const int l7  = lane & 7;
    const int l8  = (lane >> 3) & 1;
    const int l16 = (lane >> 4) & 1;
    uint32_t aoff[2][2], boff[2][2];
    #pragma unroll
    for (int ma = 0; ma < 2; ma++)
        #pragma unroll
        for (int ks = 0; ks < 2; ks++) {
            int row  = wm * 32 + ma * 16 + l8 * 8 + l7;
            int colh = l16 * 8 + ks * 16;
            aoff[ma][ks] = (row * AS_H + colh) * 2;
        }
    #pragma unroll
    for (int p = 0; p < 2; p++)
        #pragma unroll
        for (int ks = 0; ks < 2; ks++) {
            int nrow = wn * 32 + p * 16 + l16 * 8 + l7;
            int colh = l8 * 8 + ks * 16;
            boff[p][ks] = A_BUF_H * 2 + (nrow * AS_H + colh) * 2;
        }

    // loader: one 16B A-chunk + one 16B B-chunk per thread per ktile
    const int cr = tid >> 2;
    const int cu = tid & 3;
    const bool b_ok = (colBase + cr) < N;

    auto issue = [&](int kt) {
        int st = kt & (STAGES - 1);
        uint32_t sa = sbase + st * STAGE_H * 2;
        uint32_t sb = sa + A_BUF_H * 2;
        const __half* ga = A + (size_t)(rowBase + cr) * K + kt * TBK + cu * 8;
        cp_async16(sa + (cr * AS_H + cu * 8) * 2, ga, true);
        const __half* gb = Bt + (size_t)(colBase + cr) * K + kt * TBK + cu * 8;
        cp_async16(sb + (cr * AS_H + cu * 8) * 2, gb, b_ok);
        cp_commit();
    };

    float acc[2][4][4];
    #pragma unroll
    for (int i = 0; i < 2; i++)
        #pragma unroll
        for (int j = 0; j < 4; j++)
            #pragma unroll
            for (int r = 0; r < 4; r++) acc[i][j][r] = 0.0f;

    auto compute = [&](int st) {
        uint32_t sa = sbase + st * STAGE_H * 2;
        #pragma unroll
        for (int ks = 0; ks < 2; ks++) {
            uint32_t af[2][4], bf[4][2], r0[4], r1[4];
            ldsm4(af[0], sa + aoff[0][ks]);
            ldsm4(af[1], sa + aoff[1][ks]);
            ldsm4(r0, sa + boff[0][ks]);
            ldsm4(r1, sa + boff[1][ks]);
            bf[0][0] = r0[0]; bf[0][1] = r0[1];
            bf[1][0] = r0[2]; bf[1][1] = r0[3];
            bf[2][0] = r1[0]; bf[2][1] = r1[1];
            bf[3][0] = r1[2]; bf[3][1] = r1[3];
            #pragma unroll
            for (int ma = 0; ma < 2; ma++)
                #pragma unroll
                for (int nb = 0; nb < 4; nb++)
                    mma_f16(acc[ma][nb], af[ma], bf[nb]);
        }
    };

    const int ktiles = K / TBK;
    const int pre = ktiles < 3 ? ktiles : 3;
    for (int i = 0; i < pre; i++) issue(i);
    for (int i = pre; i < 3; i++) cp_commit();

    for (int kt = 0; kt < ktiles; kt++) {
        cp_wait<2>();
        __syncthreads();
        int nk = kt + 3;
        if (nk < ktiles) issue(nk); else cp_commit();
        compute(kt & (STAGES - 1));
    }

    // ---- epilogue
    float*  Cf = reinterpret_cast<float*>(Cv);
    __half* Ch = reinterpret_cast<__half*>(Cv);
    #pragma unroll
    for (int ma = 0; ma < 2; ma++) {
        int row0 = rowBase + wm * 32 + ma * 16 + grp;
        #pragma unroll
        for (int nb = 0; nb < 4; nb++) {
            int col0 = colBase + wn * 32 + nb * 8 + qid * 2;
            #pragma unroll
            for (int half_i = 0; half_i < 2; half_i++) {
                int row = row0 + half_i * 8;
                #pragma unroll
                for (int j = 0; j < 2; j++) {
                    int col = col0 + j;
                    if (col < N) {
                        float v = acc[ma][nb][half_i * 2 + j];
                        if (EPI >= 1) v += bias[col];
                        if (EPI == 3) v += res[(size_t)row * N + col];
                        if (EPI == 2) v = fmaxf(v, 0.0f);
                        if (OUT_HALF) Ch[(size_t)row * N + col] = __float2half_rn(v);
                        else          Cf[(size_t)row * N + col] = v;
                    }
                }
            }
        }
    }
}

// ---------------------------------------------------------------------------
// Fused causal attention, chunked online softmax (rescale once per 16 keys).
// One block per (head,batch), one thread per query. scale = C^-0.5 = 1/16.
// ---------------------------------------------------------------------------
__global__ void __launch_bounds__(128)
attn_kernel(const float* __restrict__ qkv, __half* __restrict__ out) {
    __shared__ __align__(16) float Ks[64 * HSn];
    __shared__ __align__(16) float Vs[64 * HSn];

    const int h  = blockIdx.x;
    const int b  = blockIdx.y;
    const int tq = threadIdx.x;
    const int token = b * Tn + tq;

    float qr[HSn];
    #pragma unroll
    for (int d = 0; d < HSn; d += 4) {
        float4 t4 = *reinterpret_cast<const float4*>(
            &qkv[(size_t)token * QKVN + h * HSn + d]);
        qr[d] = t4.x; qr[d + 1] = t4.y; qr[d + 2] = t4.z; qr[d + 3] = t4.w;
    }

    float m = -1e30f, l = 0.0f;
    float acc[HSn];
    #pragma unroll
    for (int d = 0; d < HSn; d++) acc[d] = 0.0f;

    const int r    = tq >> 1;
    const int half = (tq & 1) * 32;

    for (int ch = 0; ch < 2; ch++) {
        __syncthreads();
        int tok2 = b * Tn + ch * 64 + r;
        #pragma unroll
        for (int d = 0; d < 32; d += 4) {
            int col = half + d;
            *reinterpret_cast<float4*>(&Ks[r * HSn + col]) =
                *reinterpret_cast<const float4*>(
                    &qkv[(size_t)tok2 * QKVN + Cn + h * HSn + col]);
            *reinterpret_cast<float4*>(&Vs[r * HSn + col]) =
                *reinterpret_cast<const float4*>(
                    &qkv[(size_t)tok2 * QKVN + 2 * Cn + h * HSn + col]);
        }
        __syncthreads();

        for (int sub = 0; sub < 4; sub++) {
            int t0 = sub * 16;                        // within-chunk key base
            int nv = tq - (ch * 64 + t0) + 1;         // #causal-valid keys
            if (nv <= 0) break;
            nv = nv < 16 ? nv : 16;

            float s[16];
            float cmax = -1e30f;
            for (int i = 0; i < nv; i++) {
                float dot = 0.0f;
                #pragma unroll
                for (int d = 0; d < HSn; d++)
                    dot = fmaf(qr[d], Ks[(t0 + i) * HSn + d], dot);
                s[i] = dot * 0.0625f;
                cmax = fmaxf(cmax, s[i]);
            }

            float mn   = fmaxf(m, cmax);
            float corr = __expf(m - mn);
            l *= corr;
            #pragma unroll
            for (int d = 0; d < HSn; d++) acc[d] *= corr;

            for (int i = 0; i < nv; i++) {
                float p = __expf(s[i] - mn);
                l += p;
                #pragma unroll
                for (int d = 0; d < HSn; d++)
                    acc[d] = fmaf(p, Vs[(t0 + i) * HSn + d], acc[d]);
            }
            m = mn;
        }
    }

    float inv = 1.0f / l;
    #pragma unroll
    for (int d = 0; d < HSn; d++)
        out[(size_t)token * Cn + h * HSn + d] = __float2half_rn(acc[d] * inv);
}

// ---------------------------------------------------------------------------
// Host driver (graph-capturable)
// ---------------------------------------------------------------------------
extern "C" void kernel_launch(void* const* d_in, const int* in_sizes, int n_in,
                              void* d_out, int out_size) {
    const int*   idx     = (const int*)  d_in[0];
    const float* tok_emb = (const float*)d_in[1];
    const float* pos_emb = (const float*)d_in[2];
    const float* ln1_g   = (const float*)d_in[3];
    const float* ln1_b   = (const float*)d_in[4];
    const float* wq      = (const float*)d_in[5];
    const float* wk      = (const float*)d_in[6];
    const float* wv      = (const float*)d_in[7];
    const float* proj_w  = (const float*)d_in[8];
    const float* proj_b  = (const float*)d_in[9];
    const float* ln2_g   = (const float*)d_in[10];
    const float* ln2_b   = (const float*)d_in[11];
    const float* w1      = (const float*)d_in[12];
    const float* b1      = (const float*)d_in[13];
    const float* w2      = (const float*)d_in[14];
    const float* b2      = (const float*)d_in[15];
    const float* lnf_g   = (const float*)d_in[16];
    const float* lnf_b   = (const float*)d_in[17];
    const float* lm_w    = (const float*)d_in[18];
    const float* lm_b    = (const float*)d_in[19];
    float*       out     = (float*)d_out;

    float  *x, *qkvb;
    __half *h, *att, *ffn, *qkvw, *projw, *w1t, *w2t, *lmt;
    cudaGetSymbolAddress((void**)&x,     g_x);
    cudaGetSymbolAddress((void**)&h,     g_h);
    cudaGetSymbolAddress((void**)&qkvb,  g_qkv);
    cudaGetSymbolAddress((void**)&att,   g_att);
    cudaGetSymbolAddress((void**)&ffn,   g_ffn);
    cudaGetSymbolAddress((void**)&qkvw,  g_qkvw);
    cudaGetSymbolAddress((void**)&projw, g_projw);
    cudaGetSymbolAddress((void**)&w1t,   g_w1);
    cudaGetSymbolAddress((void**)&w2t,   g_w2);
    cudaGetSymbolAddress((void**)&lmt,   g_lmw);

    cudaFuncSetAttribute(hgemm_kernel<0,false>, cudaFuncAttributeMaxDynamicSharedMemorySize, GEMM_SMEM_B);
    cudaFuncSetAttribute(hgemm_kernel<1,false>, cudaFuncAttributeMaxDynamicSharedMemorySize, GEMM_SMEM_B);
    cudaFuncSetAttribute(hgemm_kernel<2,true >, cudaFuncAttributeMaxDynamicSharedMemorySize, GEMM_SMEM_B);
    cudaFuncSetAttribute(hgemm_kernel<3,false>, cudaFuncAttributeMaxDynamicSharedMemorySize, GEMM_SMEM_B);

    // --- fused weight prepack (single launch)
    {
        TrtPack p;
        int base = 0;
        auto mk = [&](const float* s, __half* d, int K, int N, int nz,
                      long long ss, long long ds) {
            int nx = (N + 31) / 32, ny = (K + 31) / 32;
            TrtJob J{s, d, K, N, nx, ny, ss, ds, base, nx * ny * nz};
            base += J.count;
            return J;
        };
        p.j[0] = mk(wq,     qkvw,               Cn, Cn,  Ln, (long long)Cn * Cn,   (long long)QKVN * Cn);
        p.j[1] = mk(wk,     qkvw + Cn * Cn,     Cn, Cn,  Ln, (long long)Cn * Cn,   (long long)QKVN * Cn);
        p.j[2] = mk(wv,     qkvw + 2 * Cn * Cn, Cn, Cn,  Ln, (long long)Cn * Cn,   (long long)QKVN * Cn);
        p.j[3] = mk(proj_w, projw,              Cn, Cn,  Ln, (long long)Cn * Cn,   (long long)Cn * Cn);
        p.j[4] = mk(w1,     w1t,                Cn, DFFn, Ln, (long long)Cn * DFFn, (long long)Cn * DFFn);
        p.j[5] = mk(w2,     w2t,                DFFn, Cn, Ln, (long long)Cn * DFFn, (long long)Cn * DFFn);
        p.j[6] = mk(lm_w,   lmt,                Cn, Vn,  1,  (long long)Cn * Vn,   (long long)Cn * Vn);
        trt_all<<<base, dim3(32, 8)>>>(p);
    }

    embed_kernel<<<NTOK, Cn>>>(idx, tok_emb, pos_emb);

    dim3 gridQKV(QKVN / TBN,           NTOK / TBM);   // (6, 128)
    dim3 gridC  (Cn / TBN,             NTOK / TBM);   // (2, 128)
    dim3 gridF  (DFFn / TBN,           NTOK / TBM);   // (8, 128)
    dim3 gridV  ((Vn + TBN - 1) / TBN, NTOK / TBM);   // (79, 128)
    dim3 gridA  (Hn, Bn);

    for (int l = 0; l < Ln; l++) {
        const __half* Wqkv = qkvw  + (size_t)l * Cn * QKVN;
        const __half* Wp   = projw + (size_t)l * Cn * Cn;
        const __half* W1   = w1t   + (size_t)l * Cn * DFFn;
        const __half* W2   = w2t   + (size_t)l * DFFn * Cn;

        ln_kernel<<<NTOK, Cn>>>(x, ln1_g + l * Cn, ln1_b + l * Cn, h);

        hgemm_kernel<0,false><<<gridQKV, 512, GEMM_SMEM_B>>>(
            h, Wqkv, nullptr, nullptr, qkvb, NTOK, QKVN, Cn);

        attn_kernel<<<gridA, 128>>>(qkvb, att);

        hgemm_kernel<3,false><<<gridC, 512, GEMM_SMEM_B>>>(
            att, Wp, proj_b + l * Cn, x, x, NTOK, Cn, Cn);

        ln_kernel<<<NTOK, Cn>>>(x, ln2_g + l * Cn, ln2_b + l * Cn, h);

        hgemm_kernel<2,true><<<gridF, 512, GEMM_SMEM_B>>>(
            h, W1, b1 + l * DFFn, nullptr, ffn, NTOK, DFFn, Cn);
        hgemm_kernel<3,false><<<gridC, 512, GEMM_SMEM_B>>>(
            ffn, W2, b2 + l * Cn, x, x, NTOK, Cn, DFFn);
    }

    ln_kernel<<<NTOK, Cn>>>(x, lnf_g, lnf_b, h);
    hgemm_kernel<1,false><<<gridV, 512, GEMM_SMEM_B>>>(
        h, lmt, lm_b, nullptr, out, NTOK, Vn, Cn);
}